// round 6
// baseline (speedup 1.0000x reference)
#include <cuda_runtime.h>
#include <cuda_fp16.h>
#include <cstdint>

// Problem constants
#define SRC  2048
#define TGT  2048
#define BB   16
#define HH   512
#define HH2  1024

// Tiling
#define MT   32          // t-rows per CTA
#define NS   32          // s-rows per inner iteration
#define NSI  (SRC / NS)  // 64 iterations
#define HSTR 520         // half-row stride (512 + 8) -> ldmatrix conflict-free
#define PSTR 33          // fp32 score row stride (33 floats -> conflict-free softmax)
#define PSTRH 40         // fp16 P row stride (80B, 16B-aligned, ldsm conflict-free)

#define NEG_INF (-__int_as_float(0x7f800000))

// Pre-split summed encoder states [B][S][H], fp16 hi + fp16 lo planes.
__device__ __half g_hi[(size_t)BB * SRC * HH];
__device__ __half g_lo[(size_t)BB * SRC * HH];

__device__ __forceinline__ uint32_t s2u(const void* p) {
    return (uint32_t)__cvta_generic_to_shared(p);
}

__device__ __forceinline__ void cp16(uint32_t s, const void* g) {
    asm volatile("cp.async.cg.shared.global [%0], [%1], 16;" :: "r"(s), "l"(g));
}

__device__ __forceinline__ void ldm_x4(uint32_t& r0, uint32_t& r1, uint32_t& r2, uint32_t& r3,
                                       uint32_t addr) {
    asm volatile("ldmatrix.sync.aligned.m8n8.x4.shared.b16 {%0,%1,%2,%3}, [%4];"
                 : "=r"(r0), "=r"(r1), "=r"(r2), "=r"(r3) : "r"(addr));
}

__device__ __forceinline__ void ldm_x2(uint32_t& r0, uint32_t& r1, uint32_t addr) {
    asm volatile("ldmatrix.sync.aligned.m8n8.x2.shared.b16 {%0,%1}, [%2];"
                 : "=r"(r0), "=r"(r1) : "r"(addr));
}

__device__ __forceinline__ void ldm_x4t(uint32_t& r0, uint32_t& r1, uint32_t& r2, uint32_t& r3,
                                        uint32_t addr) {
    asm volatile("ldmatrix.sync.aligned.m8n8.x4.trans.shared.b16 {%0,%1,%2,%3}, [%4];"
                 : "=r"(r0), "=r"(r1), "=r"(r2), "=r"(r3) : "r"(addr));
}

__device__ __forceinline__ void mma16(float* c,
                                      uint32_t a0, uint32_t a1, uint32_t a2, uint32_t a3,
                                      uint32_t b0, uint32_t b1) {
    asm volatile(
        "mma.sync.aligned.m16n8k16.row.col.f32.f16.f16.f32 "
        "{%0,%1,%2,%3}, {%4,%5,%6,%7}, {%8,%9}, {%0,%1,%2,%3};"
        : "+f"(c[0]), "+f"(c[1]), "+f"(c[2]), "+f"(c[3])
        : "r"(a0), "r"(a1), "r"(a2), "r"(a3), "r"(b0), "r"(b1));
}

// ---------------------------------------------------------------------------
// Pre-pass: sum bidirectional halves, split into fp16 hi/lo planes.
// ---------------------------------------------------------------------------
__global__ void __launch_bounds__(256)
prep_oe_kernel(const float* __restrict__ oe_raw) {
    size_t i = (size_t)blockIdx.x * blockDim.x + threadIdx.x;   // over B*S*H/4
    const size_t total = (size_t)BB * SRC * HH / 4;
    if (i >= total) return;
    size_t c4   = i % (HH / 4);
    size_t rest = i / (HH / 4);
    size_t s = rest % SRC;
    size_t b = rest / SRC;
    const float* p = oe_raw + s * (size_t)(BB * HH2) + b * HH2 + c4 * 4;
    float4 x = *(const float4*)p;
    float4 y = *(const float4*)(p + HH);
    float v[4] = {x.x + y.x, x.y + y.y, x.z + y.z, x.w + y.w};
    __half h[4], l[4];
#pragma unroll
    for (int j = 0; j < 4; ++j) {
        h[j] = __float2half_rn(v[j]);
        l[j] = __float2half_rn(v[j] - __half2float(h[j]));
    }
    size_t o = b * (size_t)(SRC * HH) + s * HH + c4 * 4;
    *(__half2*)(g_hi + o)     = __halves2half2(h[0], h[1]);
    *(__half2*)(g_hi + o + 2) = __halves2half2(h[2], h[3]);
    *(__half2*)(g_lo + o)     = __halves2half2(l[0], l[1]);
    *(__half2*)(g_lo + o + 2) = __halves2half2(l[2], l[3]);
}

// ---------------------------------------------------------------------------
// Fused flash attention, fp16-split compensated precision, MT=32,
// double-buffered cp.async KV prefetch.
// Warp layout (8 warps): mw = wid&1 owns rows [16*mw, 16*mw+16);
//                        nw = wid>>1 owns s-cols [8*nw, 8*nw+8) for QK^T
//                        and h-cols [128*nw, 128*nw+128) for PV.
// ---------------------------------------------------------------------------
__global__ void __launch_bounds__(256, 1)
flash_kernel(const float* __restrict__ od, float* __restrict__ out) {
    extern __shared__ char smraw[];
    __half* q_hi  = (__half*)smraw;                 // 32*520
    __half* q_lo  = q_hi + MT * HSTR;
    __half* kvh   = q_lo + MT * HSTR;               // 2 stages * 32*520
    __half* kvl   = kvh + 2 * NS * HSTR;
    float*  ps    = (float*)(kvl + 2 * NS * HSTR);  // 32*33 fp32 scores
    __half* ps_h  = (__half*)(ps + MT * PSTR);      // 32*40 fp16 P
    float*  mrow  = (float*)(ps_h + MT * PSTRH);
    float*  lrow  = mrow + MT;
    float*  srow  = lrow + MT;

    const int b    = blockIdx.y;
    const int t0   = blockIdx.x * MT;
    const int tid  = threadIdx.x;
    const int lane = tid & 31;
    const int wid  = tid >> 5;
    const int g    = lane >> 2;
    const int tig  = lane & 3;
    const int mw   = wid & 1;
    const int nw   = wid >> 1;      // 0..3
    const int m0   = mw * 16;

    // --- load + split Q tile (32 rows) ---
    {
        const float* qg = od + (size_t)t0 * (BB * HH) + (size_t)b * HH;
        for (int idx = tid; idx < MT * (HH / 4); idx += 256) {
            int r = idx >> 7;               // 128 float4 per row
            int c = (idx & 127) << 2;
            float4 v = *(const float4*)(qg + (size_t)r * (BB * HH) + c);
            float vv[4] = {v.x, v.y, v.z, v.w};
            __half h[4], l[4];
#pragma unroll
            for (int j = 0; j < 4; ++j) {
                h[j] = __float2half_rn(vv[j]);
                l[j] = __float2half_rn(vv[j] - __half2float(h[j]));
            }
            int o = r * HSTR + c;
            *(__half2*)(q_hi + o)     = __halves2half2(h[0], h[1]);
            *(__half2*)(q_hi + o + 2) = __halves2half2(h[2], h[3]);
            *(__half2*)(q_lo + o)     = __halves2half2(l[0], l[1]);
            *(__half2*)(q_lo + o + 2) = __halves2half2(l[2], l[3]);
        }
    }
    if (tid < MT) { mrow[tid] = NEG_INF; lrow[tid] = 0.f; }

    float o[64];
#pragma unroll
    for (int i = 0; i < 64; ++i) o[i] = 0.f;

    // ldmatrix base addresses (bytes)
    const int a_row = m0 + ((lane >> 3) & 1) * 8 + (lane & 7);
    const int a_col = (lane >> 4) * 8;
    const uint32_t qa_hi = s2u(q_hi) + (uint32_t)(a_row * HSTR + a_col) * 2;
    const uint32_t qa_lo = s2u(q_lo) + (uint32_t)(a_row * HSTR + a_col) * 2;
    const uint32_t pa    = s2u(ps_h) + (uint32_t)(a_row * PSTRH + a_col) * 2;
    // K x2 pattern: lanes 0-15 -> rows nw*8..+8, kcol 0/8
    const uint32_t kb_off = (uint32_t)((nw * 8 + (lane & 7)) * HSTR +
                                       ((lane >> 3) & 1) * 8) * 2;
    // V x4t pattern: lanes 0-15 rows (s), lanes 16-31 shift +8 h
    const uint32_t vb_off = (uint32_t)((lane & 15) * HSTR + (lane >> 4) * 8) * 2;

    const size_t kvoff = (size_t)b * (SRC * HH);
    const uint32_t kvh_s = s2u(kvh);
    const uint32_t kvl_s = s2u(kvl);

    // prologue: prefetch tile 0 into stage 0
    {
        const __half* gh = g_hi + kvoff;
        const __half* gl = g_lo + kvoff;
        for (int u = tid; u < NS * HH / 8; u += 256) {
            int r = u >> 6;
            int c = (u & 63) << 3;
            cp16(kvh_s + (uint32_t)(r * HSTR + c) * 2, gh + r * HH + c);
            cp16(kvl_s + (uint32_t)(r * HSTR + c) * 2, gl + r * HH + c);
        }
        asm volatile("cp.async.commit_group;");
    }

    for (int si = 0; si < NSI; ++si) {
        const int cur = si & 1;
        asm volatile("cp.async.wait_group 0;");
        __syncthreads();                 // tile si visible; all warps past compute(si-1)

        // prefetch tile si+1 into other stage
        if (si + 1 < NSI) {
            const int nxt = cur ^ 1;
            const __half* gh = g_hi + kvoff + (size_t)(si + 1) * NS * HH;
            const __half* gl = g_lo + kvoff + (size_t)(si + 1) * NS * HH;
            const uint32_t dh = kvh_s + (uint32_t)(nxt * NS * HSTR) * 2;
            const uint32_t dl = kvl_s + (uint32_t)(nxt * NS * HSTR) * 2;
            for (int u = tid; u < NS * HH / 8; u += 256) {
                int r = u >> 6;
                int c = (u & 63) << 3;
                cp16(dh + (uint32_t)(r * HSTR + c) * 2, gh + r * HH + c);
                cp16(dl + (uint32_t)(r * HSTR + c) * 2, gl + r * HH + c);
            }
            asm volatile("cp.async.commit_group;");
        }

        const uint32_t kh_base = kvh_s + (uint32_t)(cur * NS * HSTR) * 2;
        const uint32_t kl_base = kvl_s + (uint32_t)(cur * NS * HSTR) * 2;

        // --- S = Q.K^T (warp tile 16x8, K=512, 3-term fp16 split) ---
        float acc[4] = {0.f, 0.f, 0.f, 0.f};
#pragma unroll 4
        for (int kk = 0; kk < HH / 16; ++kk) {
            const uint32_t off = kk * 32;
            uint32_t ah0, ah1, ah2, ah3, al0, al1, al2, al3;
            ldm_x4(ah0, ah1, ah2, ah3, qa_hi + off);
            ldm_x4(al0, al1, al2, al3, qa_lo + off);
            uint32_t kh0, kh1, kl0, kl1;
            ldm_x2(kh0, kh1, kh_base + kb_off + off);
            ldm_x2(kl0, kl1, kl_base + kb_off + off);
            mma16(acc, ah0, ah1, ah2, ah3, kh0, kh1);
            mma16(acc, ah0, ah1, ah2, ah3, kl0, kl1);
            mma16(acc, al0, al1, al2, al3, kh0, kh1);
        }
        // write scores (fp32) to smem
        {
            const int cb = nw * 8 + 2 * tig;
            ps[(m0 + g) * PSTR + cb]         = acc[0];
            ps[(m0 + g) * PSTR + cb + 1]     = acc[1];
            ps[(m0 + g + 8) * PSTR + cb]     = acc[2];
            ps[(m0 + g + 8) * PSTR + cb + 1] = acc[3];
        }
        __syncthreads();

        // --- online softmax: 8 threads per row (32 rows), 4 cols each ---
        {
            const int r = tid >> 3;
            const int q = tid & 7;
            const float* pr = ps + r * PSTR + q * 4;
            __half* prh = ps_h + r * PSTRH + q * 4;
            float p0 = pr[0], p1 = pr[1], p2 = pr[2], p3 = pr[3];
            float mx = fmaxf(fmaxf(p0, p1), fmaxf(p2, p3));
            mx = fmaxf(mx, __shfl_xor_sync(0xffffffffu, mx, 1));
            mx = fmaxf(mx, __shfl_xor_sync(0xffffffffu, mx, 2));
            mx = fmaxf(mx, __shfl_xor_sync(0xffffffffu, mx, 4));
            const float mo = mrow[r];
            const float mn = fmaxf(mo, mx);
            const float sc = __expf(mo - mn);
            p0 = __expf(p0 - mn); p1 = __expf(p1 - mn);
            p2 = __expf(p2 - mn); p3 = __expf(p3 - mn);
            float sum = (p0 + p1) + (p2 + p3);
            *(__half2*)(prh)     = __halves2half2(__float2half_rn(p0), __float2half_rn(p1));
            *(__half2*)(prh + 2) = __halves2half2(__float2half_rn(p2), __float2half_rn(p3));
            sum += __shfl_xor_sync(0xffffffffu, sum, 1);
            sum += __shfl_xor_sync(0xffffffffu, sum, 2);
            sum += __shfl_xor_sync(0xffffffffu, sum, 4);
            if (q == 0) {
                mrow[r] = mn;
                lrow[r] = lrow[r] * sc + sum;
                srow[r] = sc;
            }
        }
        __syncthreads();

        // --- rescale O (skip when no max update) ---
        {
            const float s0 = srow[m0 + g];
            const float s1 = srow[m0 + g + 8];
            if (s0 != 1.f || s1 != 1.f) {
#pragma unroll
                for (int nf = 0; nf < 16; ++nf) {
                    o[4 * nf + 0] *= s0;
                    o[4 * nf + 1] *= s0;
                    o[4 * nf + 2] *= s1;
                    o[4 * nf + 3] *= s1;
                }
            }
        }

        // --- O += P.V (M=32, N=512/4 per warp, K=32; V-hi via ldmatrix.x4.trans) ---
#pragma unroll
        for (int kk = 0; kk < NS / 16; ++kk) {
            uint32_t p0, p1, p2, p3;
            ldm_x4(p0, p1, p2, p3, pa + kk * 32);
            const uint32_t vbh = kh_base + vb_off + (uint32_t)(kk * 16 * HSTR) * 2;
#pragma unroll
            for (int nf = 0; nf < 16; nf += 2) {
                const uint32_t hb = (uint32_t)(nw * 128 + nf * 8) * 2;
                uint32_t v0, v1, v2, v3;
                ldm_x4t(v0, v1, v2, v3, vbh + hb);
                mma16(&o[4 * nf],       p0, p1, p2, p3, v0, v1);
                mma16(&o[4 * (nf + 1)], p0, p1, p2, p3, v2, v3);
            }
        }
    }

    // --- epilogue ---
    const float inv0 = 1.f / lrow[m0 + g];
    const float inv1 = 1.f / lrow[m0 + g + 8];
    float* o0 = out + (size_t)(t0 + m0 + g) * (BB * HH) + (size_t)b * HH;
    float* o1 = out + (size_t)(t0 + m0 + g + 8) * (BB * HH) + (size_t)b * HH;
#pragma unroll
    for (int nf = 0; nf < 16; ++nf) {
        const int col = nw * 128 + nf * 8 + 2 * tig;
        float2 v0 = make_float2(o[4 * nf + 0] * inv0, o[4 * nf + 1] * inv0);
        float2 v1 = make_float2(o[4 * nf + 2] * inv1, o[4 * nf + 3] * inv1);
        *(float2*)(o0 + col) = v0;
        *(float2*)(o1 + col) = v1;
    }
}

// ---------------------------------------------------------------------------
extern "C" void kernel_launch(void* const* d_in, const int* in_sizes, int n_in,
                              void* d_out, int out_size) {
    const float* oe_raw = nullptr;
    const float* od = nullptr;
    for (int i = 0; i < n_in; ++i) {
        if (in_sizes[i] == SRC * BB * HH2) oe_raw = (const float*)d_in[i];
        else if (in_sizes[i] == TGT * BB * HH) od = (const float*)d_in[i];
    }
    float* out = (float*)d_out;

    const size_t smem_bytes =
        (size_t)(MT * HSTR * 2 + 2 * NS * HSTR * 2) * sizeof(__half)  // q hi/lo + kv 2-stage hi/lo
        + (size_t)MT * PSTR * sizeof(float)
        + (size_t)MT * PSTRH * sizeof(__half)
        + 3 * MT * sizeof(float);
    cudaFuncSetAttribute(flash_kernel, cudaFuncAttributeMaxDynamicSharedMemorySize,
                         (int)smem_bytes);

    {
        const size_t total = (size_t)BB * SRC * HH / 4;
        const int threads = 256;
        const int blocks = (int)((total + threads - 1) / threads);
        prep_oe_kernel<<<blocks, threads>>>(oe_raw);
    }
    {
        dim3 grid(TGT / MT, BB);
        flash_kernel<<<grid, 256, smem_bytes>>>(od, out);
    }
}